// round 1
// baseline (speedup 1.0000x reference)
#include <cuda_runtime.h>
#include <cuda_bf16.h>
#include <cstdint>

// Problem constants
constexpr int B  = 2;
constexpr int T  = 2048;
constexpr int D  = 512;
constexpr int H  = 8;
constexpr int DK = 64;      // D / H
constexpr int L  = 2 * T - 1;  // 4095

// ---------------------------------------------------------------------------
// Scratch (no cudaMalloc allowed) — device globals
// ---------------------------------------------------------------------------
__device__ float g_qh[(size_t)B * T * D];
__device__ float g_kh[(size_t)B * T * D];
__device__ float g_vh[(size_t)B * T * D];
__device__ float g_ph[(size_t)L * D];
__device__ float g_ao[(size_t)B * T * D];

// ---------------------------------------------------------------------------
// Generic tiled GEMM: Y[M,N] = X[M,K] @ W[N,K]^T + bias[N]
// BM=BN=64, BK=32, 256 threads, 4x4 micro-tile per thread.
// ---------------------------------------------------------------------------
constexpr int GBM = 64, GBN = 64, GBK = 32;

__global__ __launch_bounds__(256)
void gemm_bias_kernel(const float* __restrict__ X, const float* __restrict__ W,
                      const float* __restrict__ bias, float* __restrict__ Y,
                      int M, int N, int K) {
    __shared__ float Xs[GBM][GBK + 1];
    __shared__ float Ws[GBN][GBK + 1];

    const int tid = threadIdx.x;
    const int tx = tid & 15, ty = tid >> 4;
    const int m0 = blockIdx.y * GBM, n0 = blockIdx.x * GBN;

    float acc[4][4] = {};

    for (int k0 = 0; k0 < K; k0 += GBK) {
        for (int i = tid; i < GBM * GBK; i += 256) {
            int r = i >> 5, c = i & 31;
            int gr = m0 + r;
            Xs[r][c] = (gr < M) ? X[(size_t)gr * K + k0 + c] : 0.f;
        }
        for (int i = tid; i < GBN * GBK; i += 256) {
            int r = i >> 5, c = i & 31;
            Ws[r][c] = W[(size_t)(n0 + r) * K + k0 + c];
        }
        __syncthreads();

#pragma unroll
        for (int kk = 0; kk < GBK; kk++) {
            float xv[4], wv[4];
#pragma unroll
            for (int i = 0; i < 4; i++) xv[i] = Xs[ty * 4 + i][kk];
#pragma unroll
            for (int j = 0; j < 4; j++) wv[j] = Ws[tx * 4 + j][kk];
#pragma unroll
            for (int i = 0; i < 4; i++)
#pragma unroll
                for (int j = 0; j < 4; j++) acc[i][j] += xv[i] * wv[j];
        }
        __syncthreads();
    }

#pragma unroll
    for (int i = 0; i < 4; i++) {
        int gr = m0 + ty * 4 + i;
        if (gr >= M) continue;
#pragma unroll
        for (int j = 0; j < 4; j++) {
            int gc = n0 + tx * 4 + j;
            float bv = bias ? bias[gc] : 0.f;
            Y[(size_t)gr * N + gc] = acc[i][j] + bv;
        }
    }
}

// ---------------------------------------------------------------------------
// Fused rel-pos flash attention.
//   score(j,m) = [ q_j.(k_m + p_l) + bu.k_m + bvb.p_l ] * 1/sqrt(DK),
//   l = T-1-j+m (always in [0, 2T-2]).
// Online softmax over key tiles of 64. One block = 64 queries of one (b,h).
// ---------------------------------------------------------------------------
constexpr int BM = 64, BN = 64;
constexpr int SP = 65;  // padded row stride in smem (bank-conflict free-ish)

// smem float offsets
constexpr int OFF_Q  = 0;
constexpr int OFF_K  = OFF_Q  + BM * SP;       // 4160
constexpr int OFF_V  = OFF_K  + BN * SP;
constexpr int OFF_PR = OFF_V  + BN * SP;
constexpr int OFF_PS = OFF_PR + BM * SP;
constexpr int OFF_CK = OFF_PS + 127 * SP;
constexpr int OFF_CP = OFF_CK + 64;
constexpr int OFF_BU = OFF_CP + 127;
constexpr int OFF_BV = OFF_BU + 64;
constexpr int SMEM_FLOATS = OFF_BV + 64;
constexpr size_t ATT_SMEM_BYTES = (size_t)SMEM_FLOATS * sizeof(float);

__global__ __launch_bounds__(256)
void attn_kernel(const float* __restrict__ qh, const float* __restrict__ kh,
                 const float* __restrict__ vh, const float* __restrict__ ph,
                 const float* __restrict__ bu, const float* __restrict__ bvb,
                 float* __restrict__ out) {
    extern __shared__ float sm[];
    float* Qs  = sm + OFF_Q;
    float* Ks  = sm + OFF_K;
    float* Vs  = sm + OFF_V;
    float* Pr  = sm + OFF_PR;
    float* Ps  = sm + OFF_PS;
    float* cKs = sm + OFF_CK;
    float* cPs = sm + OFF_CP;
    float* BUs = sm + OFF_BU;
    float* BVs = sm + OFF_BV;

    const int tid = threadIdx.x;
    const int tx = tid & 15, ty = tid >> 4;
    const int q0 = blockIdx.x * BM;
    const int bh = blockIdx.y;
    const int b = bh >> 3, h = bh & 7;

    const float* qb = qh + (size_t)b * T * D + h * DK;
    const float* kb = kh + (size_t)b * T * D + h * DK;
    const float* vb = vh + (size_t)b * T * D + h * DK;
    const float* pb = ph + h * DK;

    // load Q tile + per-head biases
    for (int i = tid; i < BM * DK; i += 256) {
        int r = i >> 6, d = i & 63;
        Qs[r * SP + d] = qb[(size_t)(q0 + r) * D + d];
    }
    if (tid < 64) {
        BUs[tid] = bu[h * DK + tid];
        BVs[tid] = bvb[h * DK + tid];
    }

    float mrow[4], lrow[4], o[4][4];
#pragma unroll
    for (int i = 0; i < 4; i++) {
        mrow[i] = -1e30f;
        lrow[i] = 0.f;
#pragma unroll
        for (int j = 0; j < 4; j++) o[i][j] = 0.f;
    }
    __syncthreads();

    const int r0 = ty * 4, c0 = tx * 4;

    for (int kt = 0; kt < T / BN; kt++) {
        const int k0 = kt * BN;
        const int base0 = T - 1 - q0 - (BM - 1) + k0;  // p-window start row

        // load K, V tiles and p-window (127 rows)
        for (int i = tid; i < BN * DK; i += 256) {
            int r = i >> 6, d = i & 63;
            Ks[r * SP + d] = kb[(size_t)(k0 + r) * D + d];
            Vs[r * SP + d] = vb[(size_t)(k0 + r) * D + d];
        }
        for (int i = tid; i < 127 * DK; i += 256) {
            int w = i >> 6, d = i & 63;
            Ps[w * SP + d] = pb[(size_t)(base0 + w) * D + d];
        }
        __syncthreads();

        // bias dot products: cK[j] = bu.k_j ; cP[w] = bvb.p_w
        for (int idx = tid; idx < 64 + 127; idx += 256) {
            float s = 0.f;
            if (idx < 64) {
#pragma unroll 8
                for (int d = 0; d < DK; d++) s += BUs[d] * Ks[idx * SP + d];
                cKs[idx] = s;
            } else {
                int w = idx - 64;
#pragma unroll 8
                for (int d = 0; d < DK; d++) s += BVs[d] * Ps[w * SP + d];
                cPs[w] = s;
            }
        }
        __syncthreads();

        // scores: s[i][j] = q_i . (k_j + p_{w}), w = 63 - (r0+i) + (c0+j)
        float s[4][4] = {};
        const int wb3 = 60 - r0 + c0;  // w for (ii=0,jj=0) minus 3
#pragma unroll 4
        for (int d = 0; d < DK; d++) {
            float qv[4], kv[4], pv[7];
#pragma unroll
            for (int i = 0; i < 4; i++) qv[i] = Qs[(r0 + i) * SP + d];
#pragma unroll
            for (int j = 0; j < 4; j++) kv[j] = Ks[(c0 + j) * SP + d];
#pragma unroll
            for (int t = 0; t < 7; t++) pv[t] = Ps[(wb3 + t) * SP + d];
#pragma unroll
            for (int i = 0; i < 4; i++)
#pragma unroll
                for (int j = 0; j < 4; j++)
                    s[i][j] += qv[i] * (kv[j] + pv[j - i + 3]);
        }
#pragma unroll
        for (int i = 0; i < 4; i++)
#pragma unroll
            for (int j = 0; j < 4; j++)
                s[i][j] = (s[i][j] + cKs[c0 + j] + cPs[wb3 + 3 - i + j]) * 0.125f;

        // online softmax (row reduction across 16 tx lanes, width-16 shfl)
#pragma unroll
        for (int i = 0; i < 4; i++) {
            float rmax = fmaxf(fmaxf(s[i][0], s[i][1]), fmaxf(s[i][2], s[i][3]));
#pragma unroll
            for (int off = 8; off > 0; off >>= 1)
                rmax = fmaxf(rmax, __shfl_xor_sync(0xffffffffu, rmax, off, 16));
            float mn = fmaxf(mrow[i], rmax);
            float corr = __expf(mrow[i] - mn);
            mrow[i] = mn;
            float rs = 0.f;
#pragma unroll
            for (int j = 0; j < 4; j++) {
                float p = __expf(s[i][j] - mn);
                Pr[(r0 + i) * SP + c0 + j] = p;
                rs += p;
            }
#pragma unroll
            for (int off = 8; off > 0; off >>= 1)
                rs += __shfl_xor_sync(0xffffffffu, rs, off, 16);
            lrow[i] = lrow[i] * corr + rs;
#pragma unroll
            for (int j = 0; j < 4; j++) o[i][j] *= corr;
        }
        __syncthreads();

        // O += P @ V
#pragma unroll 4
        for (int j = 0; j < BN; j++) {
            float pvals[4], vvals[4];
#pragma unroll
            for (int i = 0; i < 4; i++) pvals[i] = Pr[(r0 + i) * SP + j];
#pragma unroll
            for (int c = 0; c < 4; c++) vvals[c] = Vs[j * SP + c0 + c];
#pragma unroll
            for (int i = 0; i < 4; i++)
#pragma unroll
                for (int c = 0; c < 4; c++) o[i][c] += pvals[i] * vvals[c];
        }
        __syncthreads();
    }

    // finalize: divide by l, write to (B, T, D) layout for the output GEMM
#pragma unroll
    for (int i = 0; i < 4; i++) {
        float inv = 1.f / lrow[i];
        size_t row = (size_t)(b * T + q0 + r0 + i) * D + h * DK;
#pragma unroll
        for (int j = 0; j < 4; j++)
            out[row + c0 + j] = o[i][j] * inv;
    }
}

// ---------------------------------------------------------------------------
// Launch
// Inputs (metadata order):
//  0:q 1:k 2:v 3:p 4:mask(all-true, ignored) 5:Wq 6:bq 7:Wk 8:bk 9:Wv 10:bv
//  11:Wp 12:Wo 13:bo 14:bu 15:bv_bias
// ---------------------------------------------------------------------------
extern "C" void kernel_launch(void* const* d_in, const int* in_sizes, int n_in,
                              void* d_out, int out_size) {
    const float* q   = (const float*)d_in[0];
    const float* k   = (const float*)d_in[1];
    const float* v   = (const float*)d_in[2];
    const float* p   = (const float*)d_in[3];
    const float* Wq  = (const float*)d_in[5];
    const float* bq  = (const float*)d_in[6];
    const float* Wk  = (const float*)d_in[7];
    const float* bk  = (const float*)d_in[8];
    const float* Wv  = (const float*)d_in[9];
    const float* bv  = (const float*)d_in[10];
    const float* Wp  = (const float*)d_in[11];
    const float* Wo  = (const float*)d_in[12];
    const float* bo  = (const float*)d_in[13];
    const float* bu  = (const float*)d_in[14];
    const float* bvb = (const float*)d_in[15];
    float* out = (float*)d_out;

    float *qh, *kh, *vh, *ph, *ao;
    cudaGetSymbolAddress((void**)&qh, g_qh);
    cudaGetSymbolAddress((void**)&kh, g_kh);
    cudaGetSymbolAddress((void**)&vh, g_vh);
    cudaGetSymbolAddress((void**)&ph, g_ph);
    cudaGetSymbolAddress((void**)&ao, g_ao);

    cudaFuncSetAttribute(attn_kernel, cudaFuncAttributeMaxDynamicSharedMemorySize,
                         (int)ATT_SMEM_BYTES);

    const int M = B * T;  // 4096
    dim3 gblk(256);
    dim3 ggrid(D / GBN, (M + GBM - 1) / GBM);
    dim3 pgrid(D / GBN, (L + GBM - 1) / GBM);

    gemm_bias_kernel<<<ggrid, gblk>>>(q, Wq, bq, qh, M, D, D);
    gemm_bias_kernel<<<ggrid, gblk>>>(k, Wk, bk, kh, M, D, D);
    gemm_bias_kernel<<<ggrid, gblk>>>(v, Wv, bv, vh, M, D, D);
    gemm_bias_kernel<<<pgrid, gblk>>>(p, Wp, nullptr, ph, L, D, D);

    dim3 agrid(T / BM, B * H);
    attn_kernel<<<agrid, 256, ATT_SMEM_BYTES>>>(qh, kh, vh, ph, bu, bvb, ao);

    gemm_bias_kernel<<<ggrid, gblk>>>(ao, Wo, bo, out, M, D, D);
}

// round 2
// speedup vs baseline: 1.7831x; 1.7831x over previous
#include <cuda_runtime.h>
#include <cuda_bf16.h>
#include <cstdint>

// Problem constants
constexpr int B  = 2;
constexpr int T  = 2048;
constexpr int D  = 512;
constexpr int H  = 8;
constexpr int DK = 64;         // D / H
constexpr int L  = 2 * T - 1;  // 4095

// ---------------------------------------------------------------------------
// Scratch (no cudaMalloc allowed) — device globals
// ---------------------------------------------------------------------------
__device__ float g_qh[(size_t)B * T * D];
__device__ float g_kh[(size_t)B * T * D];
__device__ float g_vh[(size_t)B * T * D];
__device__ float g_ph[(size_t)L * D];
__device__ float g_ao[(size_t)B * T * D];

// ---------------------------------------------------------------------------
// TF32 helpers
// ---------------------------------------------------------------------------
__device__ __forceinline__ uint32_t f2tf(float x) {
    uint32_t u;
    asm("cvt.rna.tf32.f32 %0, %1;" : "=r"(u) : "f"(x));
    return u;
}
__device__ __forceinline__ float f2tf_f(float x) { return __uint_as_float(f2tf(x)); }

__device__ __forceinline__ void mma_tf32(float c[4], const uint32_t a[4], const uint32_t b[2]) {
    asm volatile(
        "mma.sync.aligned.m16n8k8.row.col.f32.tf32.tf32.f32 "
        "{%0,%1,%2,%3}, {%4,%5,%6,%7}, {%8,%9}, {%0,%1,%2,%3};"
        : "+f"(c[0]), "+f"(c[1]), "+f"(c[2]), "+f"(c[3])
        : "r"(a[0]), "r"(a[1]), "r"(a[2]), "r"(a[3]), "r"(b[0]), "r"(b[1]));
}

// ---------------------------------------------------------------------------
// TF32 tensor-core GEMM: Y[M,N] = X[M,K] @ W[N,K]^T + bias[N]
// Block tile 128x64, BK=32, 256 threads / 8 warps (warp tile 32x32).
// ---------------------------------------------------------------------------
constexpr int GST = 36;  // smem row stride (mod 32 == 4 -> conflict-free frag loads)

__global__ __launch_bounds__(256)
void gemm_tf32_kernel(const float* __restrict__ X, const float* __restrict__ W,
                      const float* __restrict__ bias, float* __restrict__ Y,
                      int M, int N, int K) {
    __shared__ float Xs[128 * GST];
    __shared__ float Ws[64 * GST];

    const int tid = threadIdx.x;
    const int lane = tid & 31, wid = tid >> 5;
    const int wm = wid & 3, wn = wid >> 2;          // warp tile origin
    const int m0 = blockIdx.y * 128, n0 = blockIdx.x * 64;
    const int lr = lane >> 2, lc = lane & 3;

    float acc[2][4][4] = {};

    for (int k0 = 0; k0 < K; k0 += 32) {
        for (int i = tid; i < 1024; i += 256) {        // X tile: 128 rows x 8 float4
            int r = i >> 3, c4 = (i & 7) * 4;
            int gr = m0 + r;
            float4 v = make_float4(0.f, 0.f, 0.f, 0.f);
            if (gr < M) v = *(const float4*)&X[(size_t)gr * K + k0 + c4];
            float* dst = &Xs[r * GST + c4];
            dst[0] = f2tf_f(v.x); dst[1] = f2tf_f(v.y);
            dst[2] = f2tf_f(v.z); dst[3] = f2tf_f(v.w);
        }
        for (int i = tid; i < 512; i += 256) {         // W tile: 64 rows x 8 float4
            int r = i >> 3, c4 = (i & 7) * 4;
            float4 v = *(const float4*)&W[(size_t)(n0 + r) * K + k0 + c4];
            float* dst = &Ws[r * GST + c4];
            dst[0] = f2tf_f(v.x); dst[1] = f2tf_f(v.y);
            dst[2] = f2tf_f(v.z); dst[3] = f2tf_f(v.w);
        }
        __syncthreads();

#pragma unroll
        for (int ks = 0; ks < 4; ks++) {
            const int kk = ks * 8;
            uint32_t a[2][4], bf[4][2];
#pragma unroll
            for (int mf = 0; mf < 2; mf++) {
                const float* p = &Xs[(wm * 32 + mf * 16 + lr) * GST + kk + lc];
                a[mf][0] = __float_as_uint(p[0]);
                a[mf][1] = __float_as_uint(p[8 * GST]);
                a[mf][2] = __float_as_uint(p[4]);
                a[mf][3] = __float_as_uint(p[8 * GST + 4]);
            }
#pragma unroll
            for (int nf = 0; nf < 4; nf++) {
                const float* p = &Ws[(wn * 32 + nf * 8 + lr) * GST + kk + lc];
                bf[nf][0] = __float_as_uint(p[0]);
                bf[nf][1] = __float_as_uint(p[4]);
            }
#pragma unroll
            for (int mf = 0; mf < 2; mf++)
#pragma unroll
                for (int nf = 0; nf < 4; nf++)
                    mma_tf32(acc[mf][nf], a[mf], bf[nf]);
        }
        __syncthreads();
    }

#pragma unroll
    for (int mf = 0; mf < 2; mf++) {
        const int rb = m0 + wm * 32 + mf * 16 + lr;
#pragma unroll
        for (int half = 0; half < 2; half++) {
            const int r = rb + half * 8;
            if (r >= M) continue;
#pragma unroll
            for (int nf = 0; nf < 4; nf++) {
                const int c = n0 + wn * 32 + nf * 8 + 2 * lc;
                float2 v;
                v.x = acc[mf][nf][half * 2 + 0] + (bias ? bias[c] : 0.f);
                v.y = acc[mf][nf][half * 2 + 1] + (bias ? bias[c + 1] : 0.f);
                *(float2*)&Y[(size_t)r * N + c] = v;
            }
        }
    }
}

// ---------------------------------------------------------------------------
// Rel-pos flash attention, tensor-core (TF32) version.
//  Per k-tile:  AC = Q@K^T (64x64),  BD = Q@Pwin^T (64x127),
//  s(i,j) = (AC[i][j] + bu.k_j + BD[i][w] + bvb.p_w) / 8,  w = 63 - i + j.
//  Online softmax (SIMT), P@V on tensor cores, O persists in mma fragments.
// ---------------------------------------------------------------------------
constexpr int SP   = 68;   // Q/K/V/S/P row stride (mod 32 == 4)
constexpr int BDST = 132;  // BD row stride

constexpr int OFF_Q    = 0;
constexpr int OFF_K    = OFF_Q + 64 * SP;
constexpr int OFF_V    = OFF_K + 64 * SP;
constexpr int OFF_P    = OFF_V + 64 * SP;
constexpr int OFF_S    = OFF_P + 128 * SP;
constexpr int OFF_BD   = OFF_S + 64 * SP;
constexpr int OFF_CK   = OFF_BD + 64 * BDST;
constexpr int OFF_CP   = OFF_CK + 64;
constexpr int OFF_CORR = OFF_CP + 128;
constexpr int OFF_LS   = OFF_CORR + 64;
constexpr int OFF_BU   = OFF_LS + 64;
constexpr int OFF_BV   = OFF_BU + 64;
constexpr int SMEM_FLOATS = OFF_BV + 64;
constexpr size_t ATT_SMEM_BYTES = (size_t)SMEM_FLOATS * sizeof(float);

__global__ __launch_bounds__(256)
void attn_tf32_kernel(const float* __restrict__ qh, const float* __restrict__ kh,
                      const float* __restrict__ vh, const float* __restrict__ ph,
                      const float* __restrict__ bu, const float* __restrict__ bvb,
                      float* __restrict__ out) {
    extern __shared__ float sm[];
    float* Qs  = sm + OFF_Q;
    float* Ks  = sm + OFF_K;
    float* Vs  = sm + OFF_V;
    float* Ps  = sm + OFF_P;
    float* Ss  = sm + OFF_S;
    float* BDs = sm + OFF_BD;
    float* cK  = sm + OFF_CK;
    float* cP  = sm + OFF_CP;
    float* corr = sm + OFF_CORR;
    float* LS  = sm + OFF_LS;
    float* BUs = sm + OFF_BU;
    float* BVs = sm + OFF_BV;

    const int tid = threadIdx.x;
    const int lane = tid & 31, wid = tid >> 5;
    const int wm = wid & 3, wn = wid >> 2;
    const int m0w = wm * 16, n0w = wn * 32;
    const int lr = lane >> 2, lc = lane & 3;
    const int tx = tid & 15, ty = tid >> 4;
    const int r0 = ty * 4, c0 = tx * 4;

    const int q0 = blockIdx.x * 64;
    const int bh = blockIdx.y;
    const int b = bh >> 3, h = bh & 7;

    const float* qb = qh + (size_t)b * T * D + h * DK;
    const float* kb = kh + (size_t)b * T * D + h * DK;
    const float* vb = vh + (size_t)b * T * D + h * DK;
    const float* pb = ph + h * DK;

    // Q tile (tf32-rounded)
    for (int i = tid; i < 1024; i += 256) {
        int r = i >> 4, c4 = (i & 15) * 4;
        float4 v = *(const float4*)&qb[(size_t)(q0 + r) * D + c4];
        float* dst = &Qs[r * SP + c4];
        dst[0] = f2tf_f(v.x); dst[1] = f2tf_f(v.y);
        dst[2] = f2tf_f(v.z); dst[3] = f2tf_f(v.w);
    }
    if (tid < 64) { BUs[tid] = bu[h * DK + tid]; BVs[tid] = bvb[h * DK + tid]; }

    float O[4][4] = {};
    float mrow[4], lrow[4];
#pragma unroll
    for (int i = 0; i < 4; i++) { mrow[i] = -1e30f; lrow[i] = 0.f; }

    for (int kt = 0; kt < T / 64; kt++) {
        const int k0 = kt * 64;
        const int base0 = T - 1 - q0 - 63 + k0;   // p-window start (always >= 0)

        for (int i = tid; i < 1024; i += 256) {
            int r = i >> 4, c4 = (i & 15) * 4;
            float4 kv = *(const float4*)&kb[(size_t)(k0 + r) * D + c4];
            float4 vv = *(const float4*)&vb[(size_t)(k0 + r) * D + c4];
            float* dk_ = &Ks[r * SP + c4];
            float* dv_ = &Vs[r * SP + c4];
            dk_[0] = f2tf_f(kv.x); dk_[1] = f2tf_f(kv.y);
            dk_[2] = f2tf_f(kv.z); dk_[3] = f2tf_f(kv.w);
            dv_[0] = f2tf_f(vv.x); dv_[1] = f2tf_f(vv.y);
            dv_[2] = f2tf_f(vv.z); dv_[3] = f2tf_f(vv.w);
        }
        for (int i = tid; i < 127 * 16; i += 256) {
            int w = i >> 4, c4 = (i & 15) * 4;
            float4 pv = *(const float4*)&pb[(size_t)(base0 + w) * D + c4];
            float* dst = &Ps[w * SP + c4];
            dst[0] = f2tf_f(pv.x); dst[1] = f2tf_f(pv.y);
            dst[2] = f2tf_f(pv.z); dst[3] = f2tf_f(pv.w);
        }
        if (tid < 64) Ps[127 * SP + tid] = 0.f;    // pad row for the n=120..127 frag
        __syncthreads();

        // bias dot products (written before the post-mma sync, read in softmax)
        for (int idx = tid; idx < 191; idx += 256) {
            float s = 0.f;
            if (idx < 64) {
#pragma unroll 8
                for (int d = 0; d < DK; d++) s += BUs[d] * Ks[idx * SP + d];
                cK[idx] = s;
            } else {
                int w = idx - 64;
#pragma unroll 8
                for (int d = 0; d < DK; d++) s += BVs[d] * Ps[w * SP + d];
                cP[w] = s;
            }
        }

        // --- AC (64x64) and BD (64x128) on tensor cores, A frags shared ---
        float accA[4][4] = {}, accB[8][4] = {};
#pragma unroll
        for (int ks = 0; ks < 8; ks++) {
            const int kk = ks * 8;
            uint32_t a[4];
            const float* ap = &Qs[(m0w + lr) * SP + kk + lc];
            a[0] = __float_as_uint(ap[0]);
            a[1] = __float_as_uint(ap[8 * SP]);
            a[2] = __float_as_uint(ap[4]);
            a[3] = __float_as_uint(ap[8 * SP + 4]);
#pragma unroll
            for (int nf = 0; nf < 4; nf++) {
                uint32_t bf[2];
                const float* bp = &Ks[(n0w + nf * 8 + lr) * SP + kk + lc];
                bf[0] = __float_as_uint(bp[0]);
                bf[1] = __float_as_uint(bp[4]);
                mma_tf32(accA[nf], a, bf);
            }
#pragma unroll
            for (int nf = 0; nf < 8; nf++) {
                uint32_t bf[2];
                const float* bp = &Ps[(wn * 64 + nf * 8 + lr) * SP + kk + lc];
                bf[0] = __float_as_uint(bp[0]);
                bf[1] = __float_as_uint(bp[4]);
                mma_tf32(accB[nf], a, bf);
            }
        }
        {
            const int rA = m0w + lr;
#pragma unroll
            for (int nf = 0; nf < 4; nf++) {
                const int c = n0w + nf * 8 + 2 * lc;
                Ss[rA * SP + c]       = accA[nf][0];
                Ss[rA * SP + c + 1]   = accA[nf][1];
                Ss[(rA + 8) * SP + c]     = accA[nf][2];
                Ss[(rA + 8) * SP + c + 1] = accA[nf][3];
            }
#pragma unroll
            for (int nf = 0; nf < 8; nf++) {
                const int c = wn * 64 + nf * 8 + 2 * lc;
                BDs[rA * BDST + c]       = accB[nf][0];
                BDs[rA * BDST + c + 1]   = accB[nf][1];
                BDs[(rA + 8) * BDST + c]     = accB[nf][2];
                BDs[(rA + 8) * BDST + c + 1] = accB[nf][3];
            }
        }
        __syncthreads();

        // --- softmax (SIMT, 16x16 thread grid, 4x4 per thread) ---
        {
            float s[4][4];
            const int wbase = 63 - r0 + c0;
#pragma unroll
            for (int i = 0; i < 4; i++)
#pragma unroll
                for (int j = 0; j < 4; j++) {
                    const int w = wbase + j - i;
                    s[i][j] = (Ss[(r0 + i) * SP + c0 + j] + cK[c0 + j]
                               + BDs[(r0 + i) * BDST + w] + cP[w]) * 0.125f;
                }
#pragma unroll
            for (int i = 0; i < 4; i++) {
                float rmax = fmaxf(fmaxf(s[i][0], s[i][1]), fmaxf(s[i][2], s[i][3]));
#pragma unroll
                for (int off = 8; off > 0; off >>= 1)
                    rmax = fmaxf(rmax, __shfl_xor_sync(0xffffffffu, rmax, off, 16));
                const float mn = fmaxf(mrow[i], rmax);
                const float cr = __expf(mrow[i] - mn);
                mrow[i] = mn;
                float rs = 0.f;
#pragma unroll
                for (int j = 0; j < 4; j++) {
                    float p = f2tf_f(__expf(s[i][j] - mn));
                    Ss[(r0 + i) * SP + c0 + j] = p;
                    rs += p;
                }
#pragma unroll
                for (int off = 8; off > 0; off >>= 1)
                    rs += __shfl_xor_sync(0xffffffffu, rs, off, 16);
                lrow[i] = lrow[i] * cr + rs;
                if (tx == 0) corr[r0 + i] = cr;
            }
        }
        __syncthreads();

        // --- O correction + P@V on tensor cores ---
        {
            const float cf0 = corr[m0w + lr];
            const float cf1 = corr[m0w + 8 + lr];
#pragma unroll
            for (int nf = 0; nf < 4; nf++) {
                O[nf][0] *= cf0; O[nf][1] *= cf0;
                O[nf][2] *= cf1; O[nf][3] *= cf1;
            }
#pragma unroll
            for (int ks = 0; ks < 8; ks++) {
                const int kk = ks * 8;
                uint32_t a[4];
                const float* ap = &Ss[(m0w + lr) * SP + kk + lc];
                a[0] = __float_as_uint(ap[0]);
                a[1] = __float_as_uint(ap[8 * SP]);
                a[2] = __float_as_uint(ap[4]);
                a[3] = __float_as_uint(ap[8 * SP + 4]);
#pragma unroll
                for (int nf = 0; nf < 4; nf++) {
                    uint32_t bf[2];
                    bf[0] = __float_as_uint(Vs[(kk + lc) * SP + n0w + nf * 8 + lr]);
                    bf[1] = __float_as_uint(Vs[(kk + 4 + lc) * SP + n0w + nf * 8 + lr]);
                    mma_tf32(O[nf], a, bf);
                }
            }
        }
        __syncthreads();
    }

    if (tx == 0) {
#pragma unroll
        for (int i = 0; i < 4; i++) LS[r0 + i] = lrow[i];
    }
    __syncthreads();

    {
        const float inv0 = 1.f / LS[m0w + lr];
        const float inv1 = 1.f / LS[m0w + 8 + lr];
        const size_t row0 = (size_t)(b * T + q0 + m0w + lr) * D + h * DK;
        const size_t row1 = row0 + (size_t)8 * D;
#pragma unroll
        for (int nf = 0; nf < 4; nf++) {
            const int c = n0w + nf * 8 + 2 * lc;
            float2 v0, v1;
            v0.x = O[nf][0] * inv0; v0.y = O[nf][1] * inv0;
            v1.x = O[nf][2] * inv1; v1.y = O[nf][3] * inv1;
            *(float2*)&out[row0 + c] = v0;
            *(float2*)&out[row1 + c] = v1;
        }
    }
}

// ---------------------------------------------------------------------------
// Launch.  Inputs (metadata order):
//  0:q 1:k 2:v 3:p 4:mask(all-true, ignored) 5:Wq 6:bq 7:Wk 8:bk 9:Wv 10:bv
//  11:Wp 12:Wo 13:bo 14:bu 15:bv_bias
// ---------------------------------------------------------------------------
extern "C" void kernel_launch(void* const* d_in, const int* in_sizes, int n_in,
                              void* d_out, int out_size) {
    const float* q   = (const float*)d_in[0];
    const float* k   = (const float*)d_in[1];
    const float* v   = (const float*)d_in[2];
    const float* p   = (const float*)d_in[3];
    const float* Wq  = (const float*)d_in[5];
    const float* bq  = (const float*)d_in[6];
    const float* Wk  = (const float*)d_in[7];
    const float* bk  = (const float*)d_in[8];
    const float* Wv  = (const float*)d_in[9];
    const float* bv  = (const float*)d_in[10];
    const float* Wp  = (const float*)d_in[11];
    const float* Wo  = (const float*)d_in[12];
    const float* bo  = (const float*)d_in[13];
    const float* bu  = (const float*)d_in[14];
    const float* bvb = (const float*)d_in[15];
    float* out = (float*)d_out;

    float *qh, *kh, *vh, *ph, *ao;
    cudaGetSymbolAddress((void**)&qh, g_qh);
    cudaGetSymbolAddress((void**)&kh, g_kh);
    cudaGetSymbolAddress((void**)&vh, g_vh);
    cudaGetSymbolAddress((void**)&ph, g_ph);
    cudaGetSymbolAddress((void**)&ao, g_ao);

    cudaFuncSetAttribute(attn_tf32_kernel, cudaFuncAttributeMaxDynamicSharedMemorySize,
                         (int)ATT_SMEM_BYTES);

    const int M = B * T;  // 4096
    dim3 blk(256);
    dim3 ggrid(D / 64, M / 128);
    dim3 pgrid(D / 64, (L + 127) / 128);

    gemm_tf32_kernel<<<ggrid, blk>>>(q, Wq, bq, qh, M, D, D);
    gemm_tf32_kernel<<<ggrid, blk>>>(k, Wk, bk, kh, M, D, D);
    gemm_tf32_kernel<<<ggrid, blk>>>(v, Wv, bv, vh, M, D, D);
    gemm_tf32_kernel<<<pgrid, blk>>>(p, Wp, nullptr, ph, L, D, D);

    dim3 agrid(T / 64, B * H);
    attn_tf32_kernel<<<agrid, 256, ATT_SMEM_BYTES>>>(qh, kh, vh, ph, bu, bvb, ao);

    gemm_tf32_kernel<<<ggrid, blk>>>(ao, Wo, bo, out, M, D, D);
}

// round 3
// speedup vs baseline: 3.3013x; 1.8515x over previous
#include <cuda_runtime.h>
#include <cuda_bf16.h>
#include <cstdint>

// Problem constants
constexpr int B  = 2;
constexpr int T  = 2048;
constexpr int D  = 512;
constexpr int H  = 8;
constexpr int DK = 64;         // D / H
constexpr int L  = 2 * T - 1;  // 4095

// ---------------------------------------------------------------------------
// Scratch (no cudaMalloc allowed) — device globals
// ---------------------------------------------------------------------------
__device__ float g_qh[(size_t)B * T * D];
__device__ float g_kh[(size_t)B * T * D];
__device__ float g_vh[(size_t)B * T * D];
__device__ float g_ph[(size_t)L * D];
__device__ float g_ao[(size_t)B * T * D];

// ---------------------------------------------------------------------------
// Helpers
// ---------------------------------------------------------------------------
__device__ __forceinline__ uint32_t f2tf(float x) {
    uint32_t u;
    asm("cvt.rna.tf32.f32 %0, %1;" : "=r"(u) : "f"(x));
    return u;
}
__device__ __forceinline__ float f2tf_f(float x) { return __uint_as_float(f2tf(x)); }

__device__ __forceinline__ void mma_tf32(float c[4], const uint32_t a[4], const uint32_t b[2]) {
    asm volatile(
        "mma.sync.aligned.m16n8k8.row.col.f32.tf32.tf32.f32 "
        "{%0,%1,%2,%3}, {%4,%5,%6,%7}, {%8,%9}, {%0,%1,%2,%3};"
        : "+f"(c[0]), "+f"(c[1]), "+f"(c[2]), "+f"(c[3])
        : "r"(a[0]), "r"(a[1]), "r"(a[2]), "r"(a[3]), "r"(b[0]), "r"(b[1]));
}

__device__ __forceinline__ uint32_t s2u(const void* p) {
    return (uint32_t)__cvta_generic_to_shared(p);
}
__device__ __forceinline__ void cp16(uint32_t dst, const void* src) {
    asm volatile("cp.async.ca.shared.global [%0], [%1], 16;" :: "r"(dst), "l"(src));
}
__device__ __forceinline__ void cp_commit() { asm volatile("cp.async.commit_group;"); }
__device__ __forceinline__ void cp_wait0()  { asm volatile("cp.async.wait_group 0;"); }

// ---------------------------------------------------------------------------
// TF32 GEMM body: Y[M,N] = X[M,K] @ W[N,K]^T + bias[N]
// 128x128 block tile, BK=32, 256 threads, cp.async double buffered.
// Raw fp32 in smem, RNA->tf32 conversion at fragment load.
// ---------------------------------------------------------------------------
constexpr int GST = 36;                 // smem row stride (mod 32 == 4)
constexpr int GEMM_BUF = 128 * GST;     // 4608 floats per buffer
constexpr size_t GEMM_SMEM_BYTES = (size_t)4 * GEMM_BUF * sizeof(float);  // 73728

__device__ __forceinline__ void gemm_body(const float* __restrict__ X,
                                          const float* __restrict__ W,
                                          const float* __restrict__ bias,
                                          float* __restrict__ Y,
                                          int M, int N, int K, float* sm) {
    float* Xs = sm;                  // 2 buffers
    float* Ws = sm + 2 * GEMM_BUF;   // 2 buffers

    const int tid = threadIdx.x;
    const int lane = tid & 31, wid = tid >> 5;
    const int wm = wid & 1, wn = wid >> 1;      // 2x4 warps
    const int m0w = wm * 64, n0w = wn * 32;
    const int lr = lane >> 2, lc = lane & 3;
    const int m0 = blockIdx.y * 128, n0 = blockIdx.x * 128;

    const int nt = K / 32;

    auto issue = [&](int t, int buf) {
        const int k0 = t * 32;
        float* Xd = Xs + buf * GEMM_BUF;
        float* Wd = Ws + buf * GEMM_BUF;
#pragma unroll
        for (int it = 0; it < 4; it++) {
            int i = tid + it * 256;
            int r = i >> 3, c4 = (i & 7) * 4;
            int gr = m0 + r;
            float* xd = &Xd[r * GST + c4];
            if (gr < M) cp16(s2u(xd), &X[(size_t)gr * K + k0 + c4]);
            else        *(float4*)xd = make_float4(0.f, 0.f, 0.f, 0.f);
            cp16(s2u(&Wd[r * GST + c4]), &W[(size_t)(n0 + r) * K + k0 + c4]);
        }
    };

    float acc[4][4][4] = {};

    issue(0, 0);
    cp_commit();

    for (int t = 0; t < nt; t++) {
        cp_wait0();
        __syncthreads();
        if (t + 1 < nt) issue(t + 1, (t + 1) & 1);
        cp_commit();

        const float* Xb = Xs + (t & 1) * GEMM_BUF;
        const float* Wb = Ws + (t & 1) * GEMM_BUF;
#pragma unroll
        for (int ks = 0; ks < 4; ks++) {
            const int kk = ks * 8;
            uint32_t a[4][4];
#pragma unroll
            for (int mf = 0; mf < 4; mf++) {
                const float* ap = &Xb[(m0w + mf * 16 + lr) * GST + kk + lc];
                a[mf][0] = f2tf(ap[0]);
                a[mf][1] = f2tf(ap[8 * GST]);
                a[mf][2] = f2tf(ap[4]);
                a[mf][3] = f2tf(ap[8 * GST + 4]);
            }
#pragma unroll
            for (int nf = 0; nf < 4; nf++) {
                const float* bp = &Wb[(n0w + nf * 8 + lr) * GST + kk + lc];
                uint32_t bf[2] = { f2tf(bp[0]), f2tf(bp[4]) };
#pragma unroll
                for (int mf = 0; mf < 4; mf++)
                    mma_tf32(acc[mf][nf], a[mf], bf);
            }
        }
        __syncthreads();
    }

#pragma unroll
    for (int mf = 0; mf < 4; mf++) {
#pragma unroll
        for (int half = 0; half < 2; half++) {
            const int r = m0 + m0w + mf * 16 + half * 8 + lr;
            if (r >= M) continue;
#pragma unroll
            for (int nf = 0; nf < 4; nf++) {
                const int c = n0 + n0w + nf * 8 + 2 * lc;
                float2 v;
                float b0 = bias ? bias[c] : 0.f;
                float b1 = bias ? bias[c + 1] : 0.f;
                v.x = acc[mf][nf][half * 2 + 0] + b0;
                v.y = acc[mf][nf][half * 2 + 1] + b1;
                *(float2*)&Y[(size_t)r * N + c] = v;
            }
        }
    }
}

__global__ __launch_bounds__(256)
void proj_gemm_kernel(const float* __restrict__ q, const float* __restrict__ k,
                      const float* __restrict__ v, const float* __restrict__ p,
                      const float* __restrict__ Wq, const float* __restrict__ Wk,
                      const float* __restrict__ Wv, const float* __restrict__ Wp,
                      const float* __restrict__ bq, const float* __restrict__ bk,
                      const float* __restrict__ bv,
                      float* __restrict__ qh, float* __restrict__ kh,
                      float* __restrict__ vh, float* __restrict__ ph) {
    extern __shared__ float sm[];
    const int z = blockIdx.z;
    const float* X = (z == 0) ? q : (z == 1) ? k : (z == 2) ? v : p;
    const float* W = (z == 0) ? Wq : (z == 1) ? Wk : (z == 2) ? Wv : Wp;
    const float* bias = (z == 0) ? bq : (z == 1) ? bk : (z == 2) ? bv : nullptr;
    float* Y = (z == 0) ? qh : (z == 1) ? kh : (z == 2) ? vh : ph;
    const int M = (z == 3) ? L : B * T;
    gemm_body(X, W, bias, Y, M, D, D, sm);
}

__global__ __launch_bounds__(256)
void out_gemm_kernel(const float* __restrict__ X, const float* __restrict__ W,
                     const float* __restrict__ bias, float* __restrict__ Y) {
    extern __shared__ float sm[];
    gemm_body(X, W, bias, Y, B * T, D, D, sm);
}

// ---------------------------------------------------------------------------
// Rel-pos flash attention (TF32 tensor cores), BD ring buffer + cp.async.
//  Q1 = tf32(q + bu), Q2 = tf32(q + bvb).
//  Per k-tile kt: AC = Q1@K^T (64x64);  BD chunk kt+1 = Q2@Pchunk^T (64x64)
//  into a 128-col ring;  s(i,j) = (AC + BD[ring (63-i+j+64kt)&127]) / 8.
//  Online softmax; P@V on tensor cores; O in fragments.
// ---------------------------------------------------------------------------
constexpr int SP   = 68;
constexpr int BDST = 132;
constexpr int A_TILE = 64 * SP;  // 4352 floats

constexpr int OFF_Q1   = 0;
constexpr int OFF_Q2   = OFF_Q1 + A_TILE;
constexpr int OFF_K    = OFF_Q2 + A_TILE;       // 2 buffers
constexpr int OFF_V    = OFF_K + 2 * A_TILE;    // 2 buffers
constexpr int OFF_P    = OFF_V + 2 * A_TILE;    // 2 buffers
constexpr int OFF_S    = OFF_P + 2 * A_TILE;
constexpr int OFF_BD   = OFF_S + A_TILE;        // 64 x 132
constexpr int OFF_CORR = OFF_BD + 64 * BDST;
constexpr int OFF_LS   = OFF_CORR + 64;
constexpr int ATT_FLOATS = OFF_LS + 64;
constexpr size_t ATT_SMEM_BYTES = (size_t)ATT_FLOATS * sizeof(float);  // ~187KB

__global__ __launch_bounds__(256)
void attn_tf32_kernel(const float* __restrict__ qh, const float* __restrict__ kh,
                      const float* __restrict__ vh, const float* __restrict__ ph,
                      const float* __restrict__ bu, const float* __restrict__ bvb,
                      float* __restrict__ out) {
    extern __shared__ float sm[];
    float* Q1s = sm + OFF_Q1;
    float* Q2s = sm + OFF_Q2;
    float* Ks  = sm + OFF_K;
    float* Vs  = sm + OFF_V;
    float* Pn  = sm + OFF_P;
    float* Ss  = sm + OFF_S;
    float* BDs = sm + OFF_BD;
    float* corr = sm + OFF_CORR;
    float* LS  = sm + OFF_LS;

    const int tid = threadIdx.x;
    const int lane = tid & 31, wid = tid >> 5;
    const int wm = wid & 3, wn = wid >> 2;
    const int m0w = wm * 16, n0w = wn * 32;
    const int lr = lane >> 2, lc = lane & 3;
    const int tx = tid & 15, ty = tid >> 4;
    const int r0 = ty * 4, c0 = tx * 4;

    const int q0 = blockIdx.x * 64;
    const int bh = blockIdx.y;
    const int b = bh >> 3, h = bh & 7;
    const int base_p = T - 1 - q0 - 63;   // >= 0

    const float* qb = qh + (size_t)b * T * D + h * DK;
    const float* kb = kh + (size_t)b * T * D + h * DK;
    const float* vb = vh + (size_t)b * T * D + h * DK;
    const float* pb = ph + h * DK;

    auto issue_kv = [&](int kt, int buf) {
        const float* kbase = kb + (size_t)(kt * 64) * D;
        const float* vbase = vb + (size_t)(kt * 64) * D;
        float* Kd = Ks + buf * A_TILE;
        float* Vd = Vs + buf * A_TILE;
#pragma unroll
        for (int it = 0; it < 4; it++) {
            int i = tid + it * 256;
            int r = i >> 4, c4 = (i & 15) * 4;
            cp16(s2u(&Kd[r * SP + c4]), kbase + (size_t)r * D + c4);
            cp16(s2u(&Vd[r * SP + c4]), vbase + (size_t)r * D + c4);
        }
    };
    auto issue_p = [&](int ch, int buf) {
        float* Pd = Pn + buf * A_TILE;
#pragma unroll
        for (int it = 0; it < 4; it++) {
            int i = tid + it * 256;
            int r = i >> 4, c4 = (i & 15) * 4;
            int g = base_p + ch * 64 + r;
            float* dst = &Pd[r * SP + c4];
            if (g < L) cp16(s2u(dst), pb + (size_t)g * D + c4);
            else       *(float4*)dst = make_float4(0.f, 0.f, 0.f, 0.f);
        }
    };

    // Q tiles with bias folding (pre-converted to tf32)
#pragma unroll
    for (int it = 0; it < 4; it++) {
        int i = tid + it * 256;
        int r = i >> 4, c4 = (i & 15) * 4;
        float4 qv  = *(const float4*)&qb[(size_t)(q0 + r) * D + c4];
        float4 bu4 = *(const float4*)&bu[h * DK + c4];
        float4 bv4 = *(const float4*)&bvb[h * DK + c4];
        float* d1 = &Q1s[r * SP + c4];
        float* d2 = &Q2s[r * SP + c4];
        d1[0] = f2tf_f(qv.x + bu4.x); d1[1] = f2tf_f(qv.y + bu4.y);
        d1[2] = f2tf_f(qv.z + bu4.z); d1[3] = f2tf_f(qv.w + bu4.w);
        d2[0] = f2tf_f(qv.x + bv4.x); d2[1] = f2tf_f(qv.y + bv4.y);
        d2[2] = f2tf_f(qv.z + bv4.z); d2[3] = f2tf_f(qv.w + bv4.w);
    }

    issue_kv(0, 0);
    issue_p(0, 0);
    issue_p(1, 1);
    cp_commit();
    cp_wait0();
    __syncthreads();

    // prologue: BD chunk 0 -> ring slot 0
    {
        const float* Pb = Pn;  // buf 0
        float accB[4][4] = {};
#pragma unroll
        for (int ks = 0; ks < 8; ks++) {
            const int kk = ks * 8;
            uint32_t a2[4];
            const float* ap = &Q2s[(m0w + lr) * SP + kk + lc];
            a2[0] = __float_as_uint(ap[0]);
            a2[1] = __float_as_uint(ap[8 * SP]);
            a2[2] = __float_as_uint(ap[4]);
            a2[3] = __float_as_uint(ap[8 * SP + 4]);
#pragma unroll
            for (int nf = 0; nf < 4; nf++) {
                const float* bp = &Pb[(n0w + nf * 8 + lr) * SP + kk + lc];
                uint32_t bf[2] = { f2tf(bp[0]), f2tf(bp[4]) };
                mma_tf32(accB[nf], a2, bf);
            }
        }
        const int rA = m0w + lr;
#pragma unroll
        for (int nf = 0; nf < 4; nf++) {
            const int c = n0w + nf * 8 + 2 * lc;   // ring slot 0 base col 0
            BDs[rA * BDST + c]           = accB[nf][0];
            BDs[rA * BDST + c + 1]       = accB[nf][1];
            BDs[(rA + 8) * BDST + c]     = accB[nf][2];
            BDs[(rA + 8) * BDST + c + 1] = accB[nf][3];
        }
    }
    __syncthreads();

    float O[4][4] = {};
    float mrow[4], lrow[4];
#pragma unroll
    for (int i = 0; i < 4; i++) { mrow[i] = -1e30f; lrow[i] = 0.f; }

    for (int kt = 0; kt < T / 64; kt++) {
        // prefetch next K/V tile and P chunk kt+2
        if (kt + 1 < T / 64) issue_kv(kt + 1, (kt + 1) & 1);
        if (kt + 2 <= 32)    issue_p(kt + 2, kt & 1);
        cp_commit();

        // --- AC (Q1 x K) -> Ss ; BD chunk kt+1 (Q2 x P) -> ring slot (kt+1)&1 ---
        {
            const float* Kb = Ks + (kt & 1) * A_TILE;
            const float* Pb = Pn + ((kt + 1) & 1) * A_TILE;
            float accA[4][4] = {}, accB[4][4] = {};
#pragma unroll
            for (int ks = 0; ks < 8; ks++) {
                const int kk = ks * 8;
                uint32_t a1[4], a2[4];
                const float* ap1 = &Q1s[(m0w + lr) * SP + kk + lc];
                a1[0] = __float_as_uint(ap1[0]);
                a1[1] = __float_as_uint(ap1[8 * SP]);
                a1[2] = __float_as_uint(ap1[4]);
                a1[3] = __float_as_uint(ap1[8 * SP + 4]);
                const float* ap2 = &Q2s[(m0w + lr) * SP + kk + lc];
                a2[0] = __float_as_uint(ap2[0]);
                a2[1] = __float_as_uint(ap2[8 * SP]);
                a2[2] = __float_as_uint(ap2[4]);
                a2[3] = __float_as_uint(ap2[8 * SP + 4]);
#pragma unroll
                for (int nf = 0; nf < 4; nf++) {
                    const float* bp = &Kb[(n0w + nf * 8 + lr) * SP + kk + lc];
                    uint32_t bf[2] = { f2tf(bp[0]), f2tf(bp[4]) };
                    mma_tf32(accA[nf], a1, bf);
                }
#pragma unroll
                for (int nf = 0; nf < 4; nf++) {
                    const float* bp = &Pb[(n0w + nf * 8 + lr) * SP + kk + lc];
                    uint32_t bf[2] = { f2tf(bp[0]), f2tf(bp[4]) };
                    mma_tf32(accB[nf], a2, bf);
                }
            }
            const int rA = m0w + lr;
            const int slotc = ((kt + 1) & 1) * 64;
#pragma unroll
            for (int nf = 0; nf < 4; nf++) {
                const int c = n0w + nf * 8 + 2 * lc;
                Ss[rA * SP + c]           = accA[nf][0];
                Ss[rA * SP + c + 1]       = accA[nf][1];
                Ss[(rA + 8) * SP + c]     = accA[nf][2];
                Ss[(rA + 8) * SP + c + 1] = accA[nf][3];
                BDs[rA * BDST + slotc + c]           = accB[nf][0];
                BDs[rA * BDST + slotc + c + 1]       = accB[nf][1];
                BDs[(rA + 8) * BDST + slotc + c]     = accB[nf][2];
                BDs[(rA + 8) * BDST + slotc + c + 1] = accB[nf][3];
            }
        }
        __syncthreads();

        // --- softmax ---
        {
            const int wof = 63 - r0 + c0 + kt * 64;
            float s[4][4];
#pragma unroll
            for (int i = 0; i < 4; i++)
#pragma unroll
                for (int j = 0; j < 4; j++) {
                    const int wr = (wof + j - i) & 127;
                    s[i][j] = (Ss[(r0 + i) * SP + c0 + j]
                               + BDs[(r0 + i) * BDST + wr]) * 0.125f;
                }
#pragma unroll
            for (int i = 0; i < 4; i++) {
                float rmax = fmaxf(fmaxf(s[i][0], s[i][1]), fmaxf(s[i][2], s[i][3]));
#pragma unroll
                for (int off = 8; off > 0; off >>= 1)
                    rmax = fmaxf(rmax, __shfl_xor_sync(0xffffffffu, rmax, off, 16));
                const float mn = fmaxf(mrow[i], rmax);
                const float cr = __expf(mrow[i] - mn);
                mrow[i] = mn;
                float rs = 0.f;
#pragma unroll
                for (int j = 0; j < 4; j++) {
                    float pz = f2tf_f(__expf(s[i][j] - mn));
                    Ss[(r0 + i) * SP + c0 + j] = pz;
                    rs += pz;
                }
#pragma unroll
                for (int off = 8; off > 0; off >>= 1)
                    rs += __shfl_xor_sync(0xffffffffu, rs, off, 16);
                lrow[i] = lrow[i] * cr + rs;
                if (tx == 0) corr[r0 + i] = cr;
            }
        }
        __syncthreads();

        // --- O correction + P@V ---
        {
            const float* Vb = Vs + (kt & 1) * A_TILE;
            const float cf0 = corr[m0w + lr];
            const float cf1 = corr[m0w + 8 + lr];
#pragma unroll
            for (int nf = 0; nf < 4; nf++) {
                O[nf][0] *= cf0; O[nf][1] *= cf0;
                O[nf][2] *= cf1; O[nf][3] *= cf1;
            }
#pragma unroll
            for (int ks = 0; ks < 8; ks++) {
                const int kk = ks * 8;
                uint32_t a[4];
                const float* ap = &Ss[(m0w + lr) * SP + kk + lc];
                a[0] = __float_as_uint(ap[0]);
                a[1] = __float_as_uint(ap[8 * SP]);
                a[2] = __float_as_uint(ap[4]);
                a[3] = __float_as_uint(ap[8 * SP + 4]);
#pragma unroll
                for (int nf = 0; nf < 4; nf++) {
                    uint32_t bf[2];
                    bf[0] = f2tf(Vb[(kk + lc) * SP + n0w + nf * 8 + lr]);
                    bf[1] = f2tf(Vb[(kk + 4 + lc) * SP + n0w + nf * 8 + lr]);
                    mma_tf32(O[nf], a, bf);
                }
            }
        }
        cp_wait0();
        __syncthreads();
    }

    if (tx == 0) {
#pragma unroll
        for (int i = 0; i < 4; i++) LS[r0 + i] = lrow[i];
    }
    __syncthreads();

    {
        const float inv0 = 1.f / LS[m0w + lr];
        const float inv1 = 1.f / LS[m0w + 8 + lr];
        const size_t row0 = (size_t)(b * T + q0 + m0w + lr) * D + h * DK;
        const size_t row1 = row0 + (size_t)8 * D;
#pragma unroll
        for (int nf = 0; nf < 4; nf++) {
            const int c = n0w + nf * 8 + 2 * lc;
            float2 v0, v1;
            v0.x = O[nf][0] * inv0; v0.y = O[nf][1] * inv0;
            v1.x = O[nf][2] * inv1; v1.y = O[nf][3] * inv1;
            *(float2*)&out[row0 + c] = v0;
            *(float2*)&out[row1 + c] = v1;
        }
    }
}

// ---------------------------------------------------------------------------
// Launch.  Inputs (metadata order):
//  0:q 1:k 2:v 3:p 4:mask(all-true, ignored) 5:Wq 6:bq 7:Wk 8:bk 9:Wv 10:bv
//  11:Wp 12:Wo 13:bo 14:bu 15:bv_bias
// ---------------------------------------------------------------------------
extern "C" void kernel_launch(void* const* d_in, const int* in_sizes, int n_in,
                              void* d_out, int out_size) {
    const float* q   = (const float*)d_in[0];
    const float* k   = (const float*)d_in[1];
    const float* v   = (const float*)d_in[2];
    const float* p   = (const float*)d_in[3];
    const float* Wq  = (const float*)d_in[5];
    const float* bq  = (const float*)d_in[6];
    const float* Wk  = (const float*)d_in[7];
    const float* bk  = (const float*)d_in[8];
    const float* Wv  = (const float*)d_in[9];
    const float* bv  = (const float*)d_in[10];
    const float* Wp  = (const float*)d_in[11];
    const float* Wo  = (const float*)d_in[12];
    const float* bo  = (const float*)d_in[13];
    const float* bu  = (const float*)d_in[14];
    const float* bvb = (const float*)d_in[15];
    float* out = (float*)d_out;

    float *qh, *kh, *vh, *ph, *ao;
    cudaGetSymbolAddress((void**)&qh, g_qh);
    cudaGetSymbolAddress((void**)&kh, g_kh);
    cudaGetSymbolAddress((void**)&vh, g_vh);
    cudaGetSymbolAddress((void**)&ph, g_ph);
    cudaGetSymbolAddress((void**)&ao, g_ao);

    cudaFuncSetAttribute(proj_gemm_kernel, cudaFuncAttributeMaxDynamicSharedMemorySize,
                         (int)GEMM_SMEM_BYTES);
    cudaFuncSetAttribute(out_gemm_kernel, cudaFuncAttributeMaxDynamicSharedMemorySize,
                         (int)GEMM_SMEM_BYTES);
    cudaFuncSetAttribute(attn_tf32_kernel, cudaFuncAttributeMaxDynamicSharedMemorySize,
                         (int)ATT_SMEM_BYTES);

    const int M = B * T;  // 4096

    dim3 blk(256);
    dim3 pjgrid(D / 128, (M + 127) / 128, 4);   // covers M=4096 and L=4095
    proj_gemm_kernel<<<pjgrid, blk, GEMM_SMEM_BYTES>>>(
        q, k, v, p, Wq, Wk, Wv, Wp, bq, bk, bv, qh, kh, vh, ph);

    dim3 agrid(T / 64, B * H);
    attn_tf32_kernel<<<agrid, 256, ATT_SMEM_BYTES>>>(qh, kh, vh, ph, bu, bvb, ao);

    dim3 ogrid(D / 128, M / 128, 1);
    out_gemm_kernel<<<ogrid, blk, GEMM_SMEM_BYTES>>>(ao, Wo, bo, out);
}